// round 1
// baseline (speedup 1.0000x reference)
#include <cuda_runtime.h>
#include <math.h>

#define NB 32
#define DIM 4096
#define NKV 8
#define NREP 4
#define HD 128
#define MAXSEQ 2048
#define NCHUNK 8
#define CHUNK 256

// ------------------------- device scratch (no allocs allowed) ---------------
__device__ float g_q[NB * DIM];                          // rope'd Q
__device__ float g_k[NB * NKV * HD];                     // rope'd new K row
__device__ float g_v[NB * NKV * HD];                     // new V row
__device__ float g_attn[NB * DIM];                       // attention output
__device__ float g_part[4 * NB * DIM];                   // split-K partials (524288 f)
__device__ float g_pout[NB * NKV * NREP * NCHUNK * HD];  // attn partial outs
__device__ float g_ml[NB * NKV * NREP * NCHUNK * 2];     // (m, l) per chunk

// ------------------------- projection GEMM ---------------------------------
// out_part[split][b][j] = sum_{k in split-range} A[b][k] * W[j][k]
// blockDim = 128, TJ = 64 columns/block, thread tile 4b x 4j, CK = 64.
__global__ __launch_bounds__(128) void proj_kernel(
    const float* __restrict__ A,   // NB x 4096 activations (nullptr -> g_attn)
    const float* __restrict__ W0,
    const float* __restrict__ W1,
    const float* __restrict__ W2,
    int njb, int r1, int r2, int klen, int totalj)
{
    __shared__ float As[32][68];
    __shared__ float Ws[64][68];

    const float* Ap = A ? A : g_attn;

    int jb    = blockIdx.x % njb;
    int split = blockIdx.x / njb;
    int j0    = jb * 64;

    const float* W;
    int jw;
    if (j0 < r1)      { W = W0; jw = j0; }
    else if (j0 < r2) { W = W1; jw = j0 - r1; }
    else              { W = W2; jw = j0 - r2; }

    int tid = threadIdx.x;
    int jj  = tid & 15;   // 16 column groups (stride-16 columns)
    int bg  = tid >> 4;   // 8 batch groups (stride-8 batches)

    int k0 = split * klen;

    float acc[4][4];
#pragma unroll
    for (int i = 0; i < 4; i++)
#pragma unroll
        for (int j = 0; j < 4; j++) acc[i][j] = 0.f;

    for (int kc = k0; kc < k0 + klen; kc += 64) {
        __syncthreads();
        // stage A tile: 32 x 64
#pragma unroll
        for (int i = 0; i < 4; i++) {
            int s = tid + 128 * i;            // 512 float4 slots
            int bb = s >> 4, kq = s & 15;
            *(float4*)&As[bb][kq * 4] =
                *(const float4*)&Ap[(size_t)bb * 4096 + kc + kq * 4];
        }
        // stage W tile: 64 x 64
#pragma unroll
        for (int i = 0; i < 8; i++) {
            int s = tid + 128 * i;            // 1024 float4 slots
            int row = s >> 4, kq = s & 15;
            *(float4*)&Ws[row][kq * 4] =
                *(const float4*)&W[(size_t)(jw + row) * 4096 + kc + kq * 4];
        }
        __syncthreads();

#pragma unroll 4
        for (int kk = 0; kk < 64; kk += 4) {
            float4 a4[4], w4[4];
#pragma unroll
            for (int ib = 0; ib < 4; ib++)
                a4[ib] = *(const float4*)&As[bg + 8 * ib][kk];
#pragma unroll
            for (int ii = 0; ii < 4; ii++)
                w4[ii] = *(const float4*)&Ws[jj + 16 * ii][kk];
#pragma unroll
            for (int ib = 0; ib < 4; ib++)
#pragma unroll
                for (int ii = 0; ii < 4; ii++)
                    acc[ib][ii] += a4[ib].x * w4[ii].x + a4[ib].y * w4[ii].y +
                                   a4[ib].z * w4[ii].z + a4[ib].w * w4[ii].w;
        }
    }

#pragma unroll
    for (int ib = 0; ib < 4; ib++)
#pragma unroll
        for (int ii = 0; ii < 4; ii++) {
            int b = bg + 8 * ib;
            int j = j0 + jj + 16 * ii;
            g_part[(size_t)split * NB * totalj + (size_t)b * totalj + j] = acc[ib][ii];
        }
}

// ------------------------- split-K reduce + RoPE ----------------------------
__global__ void qkv_finish(const float* __restrict__ fc, const float* __restrict__ fs)
{
    int p = blockIdx.x * blockDim.x + threadIdx.x;  // pair index, 32*3072 total
    if (p >= NB * 3072) return;
    int b = p / 3072;
    int j = (p % 3072) * 2;

    float v0 = g_part[(size_t)b * 6144 + j]     + g_part[(size_t)NB * 6144 + (size_t)b * 6144 + j];
    float v1 = g_part[(size_t)b * 6144 + j + 1] + g_part[(size_t)NB * 6144 + (size_t)b * 6144 + j + 1];

    if (j < 5120) {
        int pi = (j & 127) >> 1;
        float c = fc[pi], s = fs[pi];
        float o0 = v0 * c - v1 * s;
        float o1 = v0 * s + v1 * c;
        if (j < 4096) {
            g_q[b * DIM + j]     = o0;
            g_q[b * DIM + j + 1] = o1;
        } else {
            g_k[b * 1024 + j - 4096]     = o0;
            g_k[b * 1024 + j - 4096 + 1] = o1;
        }
    } else {
        g_v[b * 1024 + j - 5120]     = v0;
        g_v[b * 1024 + j - 5120 + 1] = v1;
    }
}

// ------------------------- flash-decode attention ---------------------------
// One block per (b, kv_head, chunk). 128 threads = 4 warps.
__global__ __launch_bounds__(128) void attn_kernel(
    const float* __restrict__ cache_k, const float* __restrict__ cache_v,
    const int* __restrict__ sp)
{
    int blk = blockIdx.x;                 // c + 8*(h + 8*b)
    int c = blk & 7;
    int h = (blk >> 3) & 7;
    int b = blk >> 6;

    int tid = threadIdx.x;
    int w = tid >> 5, lane = tid & 31;

    int start_pos = *sp;
    int t_total = start_pos + 1;

    __shared__ float qs[4][HD];           // scaled q, 2KB
    __shared__ float sc[CHUNK][4];        // scores -> probs, 4KB
    __shared__ float red[4][4][HD];       // warp x rep x d, 8KB

    const float scale = 0.08838834764831845f;  // 1/sqrt(128)
    for (int i = tid; i < 4 * HD; i += 128) {
        int r = i >> 7, d = i & 127;
        qs[r][d] = g_q[(size_t)b * DIM + (h * NREP + r) * HD + d] * scale;
    }
    __syncthreads();

    int tbase = c * CHUNK;

    // phase 1: scores (each lane owns one t-row)
#pragma unroll
    for (int g = 0; g < 2; g++) {
        int tl = w * 64 + g * 32 + lane;
        int tpos = tbase + tl;
        bool valid = tpos < t_total;
        float s0 = 0.f, s1 = 0.f, s2 = 0.f, s3 = 0.f;
        if (valid) {
            const float* krow = (tpos == start_pos)
                ? &g_k[(size_t)b * 1024 + h * HD]
                : &cache_k[(((size_t)b * MAXSEQ + tpos) * NKV + h) * HD];
#pragma unroll 4
            for (int dq = 0; dq < 32; dq++) {
                float4 kv = *(const float4*)(krow + dq * 4);
                float4 q0 = *(const float4*)&qs[0][dq * 4];
                float4 q1 = *(const float4*)&qs[1][dq * 4];
                float4 q2 = *(const float4*)&qs[2][dq * 4];
                float4 q3 = *(const float4*)&qs[3][dq * 4];
                s0 += kv.x * q0.x + kv.y * q0.y + kv.z * q0.z + kv.w * q0.w;
                s1 += kv.x * q1.x + kv.y * q1.y + kv.z * q1.z + kv.w * q1.w;
                s2 += kv.x * q2.x + kv.y * q2.y + kv.z * q2.z + kv.w * q2.w;
                s3 += kv.x * q3.x + kv.y * q3.y + kv.z * q3.z + kv.w * q3.w;
            }
        } else {
            s0 = s1 = s2 = s3 = -INFINITY;
        }
        float4 sv = make_float4(s0, s1, s2, s3);
        *(float4*)&sc[tl][0] = sv;
    }
    __syncthreads();

    // phase 2: partial softmax, warp w handles rep r = w
    {
        int r = w;
        float sv[NCHUNK];
        float m = -INFINITY;
#pragma unroll
        for (int i = 0; i < 8; i++) {
            sv[i] = sc[lane + 32 * i][r];
            m = fmaxf(m, sv[i]);
        }
#pragma unroll
        for (int off = 16; off > 0; off >>= 1)
            m = fmaxf(m, __shfl_xor_sync(0xffffffffu, m, off));
        float l = 0.f;
#pragma unroll
        for (int i = 0; i < 8; i++) {
            float p = (m == -INFINITY) ? 0.f : __expf(sv[i] - m);
            sc[lane + 32 * i][r] = p;
            l += p;
        }
#pragma unroll
        for (int off = 16; off > 0; off >>= 1)
            l += __shfl_xor_sync(0xffffffffu, l, off);
        if (lane == 0) {
            size_t mlidx = ((((size_t)b * NKV + h) * NREP + r) * NCHUNK + c) * 2;
            g_ml[mlidx]     = m;
            g_ml[mlidx + 1] = l;
        }
    }
    __syncthreads();

    // phase 3: p @ V (coalesced V reads, lane owns d-quad)
    float4 acc0 = make_float4(0, 0, 0, 0), acc1 = acc0, acc2 = acc0, acc3 = acc0;
    for (int i = 0; i < 64; i++) {
        int tl = w * 64 + i;
        int tpos = tbase + tl;
        if (tpos >= t_total) break;
        const float* vrow = (tpos == start_pos)
            ? &g_v[(size_t)b * 1024 + h * HD]
            : &cache_v[(((size_t)b * MAXSEQ + tpos) * NKV + h) * HD];
        float4 vv = *(const float4*)(vrow + lane * 4);
        float4 p = *(const float4*)&sc[tl][0];
        acc0.x += p.x * vv.x; acc0.y += p.x * vv.y; acc0.z += p.x * vv.z; acc0.w += p.x * vv.w;
        acc1.x += p.y * vv.x; acc1.y += p.y * vv.y; acc1.z += p.y * vv.z; acc1.w += p.y * vv.w;
        acc2.x += p.z * vv.x; acc2.y += p.z * vv.y; acc2.z += p.z * vv.z; acc2.w += p.z * vv.w;
        acc3.x += p.w * vv.x; acc3.y += p.w * vv.y; acc3.z += p.w * vv.z; acc3.w += p.w * vv.w;
    }
    *(float4*)&red[w][0][lane * 4] = acc0;
    *(float4*)&red[w][1][lane * 4] = acc1;
    *(float4*)&red[w][2][lane * 4] = acc2;
    *(float4*)&red[w][3][lane * 4] = acc3;
    __syncthreads();

    for (int i = tid; i < 4 * HD; i += 128) {
        int r = i >> 7, d = i & 127;
        float v = red[0][r][d] + red[1][r][d] + red[2][r][d] + red[3][r][d];
        g_pout[(((((size_t)b * NKV + h) * NREP + r) * NCHUNK) + c) * HD + d] = v;
    }
}

// ------------------------- combine partial softmax --------------------------
__global__ __launch_bounds__(128) void combine_kernel()
{
    int blk = blockIdx.x;                 // r + 4*(h + 8*b)
    int r = blk & 3;
    int h = (blk >> 2) & 7;
    int b = blk >> 5;
    int d = threadIdx.x;

    size_t base = (((size_t)b * NKV + h) * NREP + r) * NCHUNK;

    float mm[NCHUNK], ll[NCHUNK];
    float mg = -INFINITY;
#pragma unroll
    for (int c = 0; c < NCHUNK; c++) {
        mm[c] = g_ml[(base + c) * 2];
        ll[c] = g_ml[(base + c) * 2 + 1];
        if (ll[c] > 0.f) mg = fmaxf(mg, mm[c]);
    }
    float L = 0.f, o = 0.f;
#pragma unroll
    for (int c = 0; c < NCHUNK; c++) {
        if (ll[c] > 0.f) {
            float f = __expf(mm[c] - mg);
            L += ll[c] * f;
            o += f * g_pout[(base + c) * HD + d];
        }
    }
    g_attn[(size_t)b * DIM + (h * NREP + r) * HD + d] = o / L;
}

// ------------------------- O-proj split-K reduce ----------------------------
__global__ void o_finish(float* __restrict__ out)
{
    int i = blockIdx.x * blockDim.x + threadIdx.x;  // 131072 elems
    if (i >= NB * DIM) return;
    out[i] = g_part[i] + g_part[(size_t)NB * DIM + i] +
             g_part[2 * (size_t)NB * DIM + i] + g_part[3 * (size_t)NB * DIM + i];
}

// ------------------------- launcher -----------------------------------------
extern "C" void kernel_launch(void* const* d_in, const int* in_sizes, int n_in,
                              void* d_out, int out_size)
{
    const float* x  = (const float*)d_in[0];
    const float* fc = (const float*)d_in[1];
    const float* fs = (const float*)d_in[2];
    const float* wq = (const float*)d_in[3];
    const float* wk = (const float*)d_in[4];
    const float* wv = (const float*)d_in[5];
    const float* wo = (const float*)d_in[6];
    const float* ck = (const float*)d_in[7];
    const float* cv = (const float*)d_in[8];
    const int*   sp = (const int*)d_in[9];
    float* out = (float*)d_out;

    // QKV projection: 6144 cols, split-K=2 -> 96*2 = 192 blocks
    proj_kernel<<<192, 128>>>(x, wq, wk, wv, 96, 4096, 5120, 2048, 6144);
    // reduce splits + RoPE
    qkv_finish<<<384, 256>>>(fc, fs);
    // attention partials: 32*8*8 = 2048 blocks
    attn_kernel<<<2048, 128>>>(ck, cv, sp);
    // combine: 32*8*4 = 1024 blocks
    combine_kernel<<<1024, 128>>>();
    // O projection: 4096 cols, split-K=4 -> 64*4 = 256 blocks (A = g_attn)
    proj_kernel<<<256, 128>>>(nullptr, wo, wo, wo, 64, 4096, 8192, 1024, 4096);
    // reduce splits -> output
    o_finish<<<512, 256>>>(out);
}